// round 8
// baseline (speedup 1.0000x reference)
#include <cuda_runtime.h>

// Problem constants
#define MROWS 8192     // B*T
#define CD    256
#define FCD   1024
#define TD    1024
#define BD    8
#define HD_   64
#define NH    4
#define NL    6
#define NOUT  192
#define QB    16
#define ATHR  512

typedef unsigned long long ull;

// ---------------- f32x2 helpers (sm_103a packed fp32) ----------------------
__device__ __forceinline__ ull pack2(float lo, float hi) {
    ull d;
    asm("mov.b64 %0, {%1, %2};" : "=l"(d) : "f"(lo), "f"(hi));
    return d;
}
__device__ __forceinline__ float2 unpack2(ull v) {
    float lo, hi;
    asm("mov.b64 {%0, %1}, %2;" : "=f"(lo), "=f"(hi) : "l"(v));
    return make_float2(lo, hi);
}
__device__ __forceinline__ void fma2(ull& d, ull a, ull b) {
    asm("fma.rn.f32x2 %0, %1, %2, %0;" : "+l"(d) : "l"(a), "l"(b));
}

// ---------------- scratch (device globals; no allocation allowed) ----------
__device__ float g_x[MROWS * CD];
__device__ float g_q[MROWS * CD];
__device__ float g_k[MROWS * CD];
__device__ float g_v[MROWS * CD];
__device__ float g_t[MROWS * CD];
__device__ float g_f[MROWS * FCD];

// ---------------- embedding ----------------
__global__ void embed_kernel(const float* __restrict__ emb,
                             const int* __restrict__ tok) {
    int idx = blockIdx.x * 256 + threadIdx.x;         // over MROWS*CD
    int m = idx >> 8;
    int c = idx & 255;
    g_x[idx] = emb[tok[m] * CD + c] * 16.0f;          // sqrt(256)
}

// ---------------- SGEMM body: Y = A[.,kOff:kOff+Kspan] @ W + (bias) --------
// tile 128x64, 128 threads, 8x8 micro, K-step 16 double-buffered, f32x2 FMA.
// K = row stride of A (total K); Kspan = this block's K range.
__device__ __forceinline__
void gemm_body(const float* __restrict__ A, const float* __restrict__ W,
               const float* __restrict__ bias, float* __restrict__ Y,
               int N, int K, int kOff, int Kspan, int relu, int addBias)
{
    __shared__ float As[2][16][128];
    __shared__ float Bs[2][16][64];
    int tid = threadIdx.x;
    int tx = tid & 7, ty = tid >> 3;
    int rowBase = blockIdx.y * 128;
    int colBase = blockIdx.x * 64;
    const float* Arow = A + (size_t)(rowBase + tid) * K + kOff;
    int e0 = tid * 2, e1 = tid * 2 + 1;
    int bk0 = e0 >> 4, bc0 = e0 & 15;
    int bk1 = e1 >> 4, bc1 = e1 & 15;
    const float* Bp0 = W + (size_t)(kOff + bk0) * N + colBase + bc0 * 4;
    const float* Bp1 = W + (size_t)(kOff + bk1) * N + colBase + bc1 * 4;

    ull acc2[8][4];
#pragma unroll
    for (int i = 0; i < 8; i++)
#pragma unroll
        for (int j = 0; j < 4; j++) acc2[i][j] = 0ull;

    // prologue: tile 0
    {
        const float4* a4 = (const float4*)Arow;
#pragma unroll
        for (int i = 0; i < 4; i++) {
            float4 v = a4[i];
            As[0][4 * i + 0][tid] = v.x; As[0][4 * i + 1][tid] = v.y;
            As[0][4 * i + 2][tid] = v.z; As[0][4 * i + 3][tid] = v.w;
        }
        *(float4*)&Bs[0][bk0][bc0 * 4] = *(const float4*)Bp0;
        *(float4*)&Bs[0][bk1][bc1 * 4] = *(const float4*)Bp1;
    }
    __syncthreads();

    int nT = Kspan >> 4;
    for (int t = 0; t < nT; t++) {
        int cur = t & 1;
        float4 ra[4], rb0, rb1;
        if (t + 1 < nT) {
            const float4* a4 = (const float4*)(Arow + (t + 1) * 16);
#pragma unroll
            for (int i = 0; i < 4; i++) ra[i] = a4[i];
            rb0 = *(const float4*)(Bp0 + (size_t)(t + 1) * 16 * N);
            rb1 = *(const float4*)(Bp1 + (size_t)(t + 1) * 16 * N);
        }
#pragma unroll
        for (int kk = 0; kk < 16; kk++) {
            float4 av0 = *(const float4*)&As[cur][kk][ty * 8];
            float4 av1 = *(const float4*)&As[cur][kk][ty * 8 + 4];
            ull bp0 = *(const ull*)&Bs[cur][kk][tx * 8];
            ull bp1 = *(const ull*)&Bs[cur][kk][tx * 8 + 2];
            ull bp2 = *(const ull*)&Bs[cur][kk][tx * 8 + 4];
            ull bp3 = *(const ull*)&Bs[cur][kk][tx * 8 + 6];
            float a[8] = {av0.x, av0.y, av0.z, av0.w, av1.x, av1.y, av1.z, av1.w};
#pragma unroll
            for (int i = 0; i < 8; i++) {
                ull ap = pack2(a[i], a[i]);
                fma2(acc2[i][0], ap, bp0);
                fma2(acc2[i][1], ap, bp1);
                fma2(acc2[i][2], ap, bp2);
                fma2(acc2[i][3], ap, bp3);
            }
        }
        if (t + 1 < nT) {
            int nxt = cur ^ 1;
#pragma unroll
            for (int i = 0; i < 4; i++) {
                As[nxt][4 * i + 0][tid] = ra[i].x; As[nxt][4 * i + 1][tid] = ra[i].y;
                As[nxt][4 * i + 2][tid] = ra[i].z; As[nxt][4 * i + 3][tid] = ra[i].w;
            }
            *(float4*)&Bs[nxt][bk0][bc0 * 4] = rb0;
            *(float4*)&Bs[nxt][bk1][bc1 * 4] = rb1;
        }
        __syncthreads();
    }

    float4 bi0 = make_float4(0.f, 0.f, 0.f, 0.f);
    float4 bi1 = make_float4(0.f, 0.f, 0.f, 0.f);
    if (addBias) {
        bi0 = *(const float4*)&bias[colBase + tx * 8];
        bi1 = *(const float4*)&bias[colBase + tx * 8 + 4];
    }
#pragma unroll
    for (int i = 0; i < 8; i++) {
        int r = rowBase + ty * 8 + i;
        float2 u0 = unpack2(acc2[i][0]);
        float2 u1 = unpack2(acc2[i][1]);
        float2 u2 = unpack2(acc2[i][2]);
        float2 u3 = unpack2(acc2[i][3]);
        float4 o0 = make_float4(u0.x + bi0.x, u0.y + bi0.y, u1.x + bi0.z, u1.y + bi0.w);
        float4 o1 = make_float4(u2.x + bi1.x, u2.y + bi1.y, u3.x + bi1.z, u3.y + bi1.w);
        if (relu) {
            o0.x = fmaxf(o0.x, 0.f); o0.y = fmaxf(o0.y, 0.f);
            o0.z = fmaxf(o0.z, 0.f); o0.w = fmaxf(o0.w, 0.f);
            o1.x = fmaxf(o1.x, 0.f); o1.y = fmaxf(o1.y, 0.f);
            o1.z = fmaxf(o1.z, 0.f); o1.w = fmaxf(o1.w, 0.f);
        }
        *(float4*)&Y[(size_t)r * N + colBase + tx * 8] = o0;
        *(float4*)&Y[(size_t)r * N + colBase + tx * 8 + 4] = o1;
    }
}

__global__ __launch_bounds__(128, 3)
void sgemm_k(const float* __restrict__ A, const float* __restrict__ W,
             const float* __restrict__ bias, float* __restrict__ Y,
             int N, int K, int relu) {
    gemm_body(A, W, bias, Y, N, K, 0, K, relu, 1);
}

// split-K=2: blockIdx.z selects K half; z=0 carries the bias; partials go to
// two separate buffers which the 3-input LN kernel sums.
__global__ __launch_bounds__(128, 3)
void sgemm_sk2(const float* __restrict__ A, const float* __restrict__ W,
               const float* __restrict__ bias,
               float* __restrict__ Y0, float* __restrict__ Y1,
               int N, int K) {
    int z = blockIdx.z;
    gemm_body(A, W, bias, z ? Y1 : Y0, N, K, z * (K >> 1), K >> 1, 0, z == 0);
}

// fused QKV: gridDim.z selects which projection
__global__ __launch_bounds__(128, 3)
void qkv_k(const float* __restrict__ A,
           const float* __restrict__ W0, const float* __restrict__ W1,
           const float* __restrict__ W2,
           const float* __restrict__ b0, const float* __restrict__ b1,
           const float* __restrict__ b2,
           float* __restrict__ Y0, float* __restrict__ Y1, float* __restrict__ Y2) {
    const float* W = (blockIdx.z == 0) ? W0 : (blockIdx.z == 1 ? W1 : W2);
    const float* bb = (blockIdx.z == 0) ? b0 : (blockIdx.z == 1 ? b1 : b2);
    float* Y = (blockIdx.z == 0) ? Y0 : (blockIdx.z == 1 ? Y1 : Y2);
    gemm_body(A, W, bb, Y, CD, CD, 0, CD, 0, 1);
}

// ---------------- fused attention (QB=16 queries per block, 512 thr) -------
// smem floats: sQ 1024 | sRelK 192 | sPart 256 | sInv 16 | sDiag 160 | sS 16384
#define ATTN_SMEM ((1024 + 192 + 256 + 16 + 160 + 16384) * 4)

__global__ __launch_bounds__(ATHR, 1)
void attn_kernel(const float* __restrict__ Q, const float* __restrict__ K,
                 const float* __restrict__ V, const float* __restrict__ relk,
                 const float* __restrict__ relv, const int* __restrict__ lens,
                 float* __restrict__ O) {
    extern __shared__ float sm[];
    float* sQ    = sm;                  // 16*64
    float* sRelK = sQ + QB * HD_;       // 16*12 (9 used, padded)
    float* sPart = sRelK + QB * 12;     // 16*16
    float* sInv  = sPart + 256;         // 16
    float* sDiag = sInv + 16;           // 16*9 (+pad to 160)
    float* sS    = sDiag + 160;         // 16*1024; later aliased as sAcc[16][16][64]

    int tid = threadIdx.x;              // 512
    int q0 = blockIdx.x * QB;
    int h  = blockIdx.y;
    int b  = blockIdx.z;
    int len = lens[b];

    // ---- load Q (scaled) ----
    for (int i = tid; i < QB * HD_; i += ATHR) {
        int qq = i >> 6, d = i & 63;
        sQ[i] = Q[((size_t)(b * TD + q0 + qq) * CD) + h * HD_ + d] * 0.125f;
    }
    __syncthreads();

    // ---- precompute q . rel_k for the 9 diagonals ----
    if (tid < QB * 9) {
        int qq = tid / 9, r = tid % 9;
        const float* rw = relk + r * HD_;
        float s = 0.f;
#pragma unroll
        for (int d = 0; d < HD_; d++) s += sQ[qq * HD_ + d] * rw[d];
        sRelK[qq * 12 + r] = s;
    }
    __syncthreads();

    // ---- scores + fused exp + partial row sums ----
    {
        const float* Kb = K + (size_t)b * TD * CD + h * HD_;
        ull acc[2][QB];
#pragma unroll
        for (int g = 0; g < 2; g++)
#pragma unroll
            for (int qq = 0; qq < QB; qq++) acc[g][qq] = 0ull;

        const float* kp0 = Kb + (size_t)tid * CD;
        const float* kp1 = Kb + (size_t)(tid + 512) * CD;
#pragma unroll 4
        for (int d4 = 0; d4 < 16; d4++) {
            ulonglong2 kv0 = *(const ulonglong2*)(kp0 + d4 * 4);
            ulonglong2 kv1 = *(const ulonglong2*)(kp1 + d4 * 4);
#pragma unroll
            for (int qq = 0; qq < QB; qq++) {
                ull qp0 = *(const ull*)&sQ[qq * HD_ + d4 * 4];
                ull qp1 = *(const ull*)&sQ[qq * HD_ + d4 * 4 + 2];
                fma2(acc[0][qq], qp0, kv0.x);
                fma2(acc[0][qq], qp1, kv0.y);
                fma2(acc[1][qq], qp0, kv1.x);
                fma2(acc[1][qq], qp1, kv1.y);
            }
        }

        float psum[QB];
#pragma unroll
        for (int qq = 0; qq < QB; qq++) psum[qq] = 0.f;
#pragma unroll
        for (int g = 0; g < 2; g++) {
            int key = tid + g * 512;
            bool kok = key < len;
#pragma unroll
            for (int qq = 0; qq < QB; qq++) {
                float2 u = unpack2(acc[g][qq]);
                float s = u.x + u.y;
                int r = key - (q0 + qq) + 4;
                if ((unsigned)r <= 8u) s += sRelK[qq * 12 + r];
                float e = (kok && (q0 + qq) < len) ? __expf(s) : 0.f;
                sS[qq * TD + key] = e;
                psum[qq] += e;
            }
        }
        int lane = tid & 31, warp = tid >> 5;
#pragma unroll
        for (int qq = 0; qq < QB; qq++) {
            float v = psum[qq];
#pragma unroll
            for (int off = 16; off > 0; off >>= 1)
                v += __shfl_xor_sync(0xffffffffu, v, off);
            if (lane == 0) sPart[qq * 16 + warp] = v;
        }
    }
    __syncthreads();

    // ---- finalize inverse sums + save diagonal probs (for rel_v) ----
    if (tid < QB) {
        float s = 0.f;
#pragma unroll
        for (int w = 0; w < 16; w++) s += sPart[tid * 16 + w];
        sInv[tid] = (s > 0.f) ? 1.0f / s : 0.f;
    }
    if (tid >= 64 && tid < 64 + QB * 9) {
        int t2 = tid - 64;
        int qq = t2 / 9, r = t2 % 9;
        int k = q0 + qq + r - 4;
        sDiag[qq * 9 + r] = (k >= 0 && k < TD) ? sS[qq * TD + k] : 0.f;
    }
    __syncthreads();

    // ---- P @ V: 16 warps x 64 keys, lane owns 2 dims (f32x2) ----
    {
        int grp = tid >> 5, lane = tid & 31;
        const float* Vb = V + (size_t)b * TD * CD + h * HD_ + lane * 2;
        ull acc[QB];
#pragma unroll
        for (int qq = 0; qq < QB; qq++) acc[qq] = 0ull;
        int kbase = grp * 64;
#pragma unroll 2
        for (int kk = 0; kk < 64; kk++) {
            int key = kbase + kk;
            ull vv = *(const ull*)(Vb + (size_t)key * CD);
#pragma unroll
            for (int qq = 0; qq < QB; qq++) {
                float p = sS[qq * TD + key];
                fma2(acc[qq], pack2(p, p), vv);
            }
        }
        __syncthreads();   // all sS reads complete before aliasing as sAcc
#pragma unroll
        for (int qq = 0; qq < QB; qq++)
            *(ull*)&sS[(grp * 16 + qq) * 64 + lane * 2] = acc[qq];
    }
    __syncthreads();

    // ---- combine groups + rel_v + write ----
    for (int i = tid; i < QB * HD_; i += ATHR) {
        int qq = i >> 6, dd = i & 63;
        float a = 0.f;
#pragma unroll
        for (int g = 0; g < 16; g++) a += sS[(g * 16 + qq) * 64 + dd];
        float inv = sInv[qq];
        a *= inv;
#pragma unroll
        for (int r = 0; r < 9; r++)
            a += sDiag[qq * 9 + r] * inv * relv[r * HD_ + dd];
        O[((size_t)(b * TD + q0 + qq) * CD) + h * HD_ + dd] = a;
    }
}

// ---------------- residual add (3-input) + LayerNorm: warp per row ---------
__global__ __launch_bounds__(256)
void add_ln3_kernel(const float* __restrict__ a, const float* __restrict__ r0,
                    const float* __restrict__ r1,
                    const float* __restrict__ g, const float* __restrict__ bb,
                    float* __restrict__ o, const int* __restrict__ lens,
                    int domask) {
    int warp = threadIdx.x >> 5, lane = threadIdx.x & 31;
    int m = blockIdx.x * 8 + warp;
    const float4* a4 = (const float4*)(a + (size_t)m * CD);
    const float4* p4 = (const float4*)(r0 + (size_t)m * CD);
    const float4* q4 = (const float4*)(r1 + (size_t)m * CD);
    float4 v0 = a4[lane * 2], v1 = a4[lane * 2 + 1];
    float4 w0 = p4[lane * 2], w1 = p4[lane * 2 + 1];
    float4 u0 = q4[lane * 2], u1 = q4[lane * 2 + 1];
    v0.x += w0.x + u0.x; v0.y += w0.y + u0.y;
    v0.z += w0.z + u0.z; v0.w += w0.w + u0.w;
    v1.x += w1.x + u1.x; v1.y += w1.y + u1.y;
    v1.z += w1.z + u1.z; v1.w += w1.w + u1.w;
    float s = v0.x + v0.y + v0.z + v0.w + v1.x + v1.y + v1.z + v1.w;
    float q = v0.x * v0.x + v0.y * v0.y + v0.z * v0.z + v0.w * v0.w +
              v1.x * v1.x + v1.y * v1.y + v1.z * v1.z + v1.w * v1.w;
#pragma unroll
    for (int off = 16; off > 0; off >>= 1) {
        s += __shfl_xor_sync(0xffffffffu, s, off);
        q += __shfl_xor_sync(0xffffffffu, q, off);
    }
    float mean = s * (1.0f / CD);
    float var = q * (1.0f / CD) - mean * mean;
    float inv = rsqrtf(var + 1e-5f);
    float4 g0 = ((const float4*)g)[lane * 2], g1 = ((const float4*)g)[lane * 2 + 1];
    float4 b0 = ((const float4*)bb)[lane * 2], b1 = ((const float4*)bb)[lane * 2 + 1];
    float4 o0, o1;
    o0.x = (v0.x - mean) * inv * g0.x + b0.x;
    o0.y = (v0.y - mean) * inv * g0.y + b0.y;
    o0.z = (v0.z - mean) * inv * g0.z + b0.z;
    o0.w = (v0.w - mean) * inv * g0.w + b0.w;
    o1.x = (v1.x - mean) * inv * g1.x + b1.x;
    o1.y = (v1.y - mean) * inv * g1.y + b1.y;
    o1.z = (v1.z - mean) * inv * g1.z + b1.z;
    o1.w = (v1.w - mean) * inv * g1.w + b1.w;
    if (domask) {
        int bb2 = m >> 10, t = m & 1023;
        if (t >= lens[bb2]) {
            o0 = make_float4(0.f, 0.f, 0.f, 0.f);
            o1 = make_float4(0.f, 0.f, 0.f, 0.f);
        }
    }
    ((float4*)(o + (size_t)m * CD))[lane * 2] = o0;
    ((float4*)(o + (size_t)m * CD))[lane * 2 + 1] = o1;
}

// ---------------- outputs ----------------
__global__ void xout_kernel(const float* __restrict__ x, float* __restrict__ ox) {
    __shared__ float tile[32][33];
    int t0 = blockIdx.x * 32, c0 = blockIdx.y * 32, b = blockIdx.z;
    int tx = threadIdx.x, ty = threadIdx.y;   // 32 x 8
    for (int i = ty; i < 32; i += 8)
        tile[i][tx] = x[((size_t)(b * TD + t0 + i) * CD) + c0 + tx];
    __syncthreads();
    for (int i = ty; i < 32; i += 8)
        ox[((size_t)(b * CD + c0 + i) * TD) + t0 + tx] = tile[tx][i];
}

__global__ void maskout_kernel(const int* __restrict__ lens, float* __restrict__ om) {
    int idx = blockIdx.x * 256 + threadIdx.x;  // over B*T
    int b = idx >> 10, t = idx & 1023;
    om[idx] = (t < lens[b]) ? 1.0f : 0.0f;
}

// 8 tokens per block: weight rows re-read 8x less from L2
__global__ __launch_bounds__(384)
void stats_kernel(const float* __restrict__ x, const float* __restrict__ pw,
                  const float* __restrict__ pb, const int* __restrict__ lens,
                  float* __restrict__ om, float* __restrict__ ol) {
    int m0 = blockIdx.x * 8;
    __shared__ float sx[8][CD];
    int tid = threadIdx.x;              // 384
    for (int i = tid; i < 8 * CD / 4; i += 384)
        ((float4*)sx)[i] = ((const float4*)(x + (size_t)m0 * CD))[i];
    __syncthreads();

    float acc[8];
#pragma unroll
    for (int t = 0; t < 8; t++) acc[t] = 0.f;
    const float4* w4 = (const float4*)(pw + (size_t)tid * CD);
#pragma unroll 8
    for (int i = 0; i < CD / 4; i++) {
        float4 w = w4[i];
#pragma unroll
        for (int t = 0; t < 8; t++) {
            float4 xv = *(const float4*)&sx[t][i * 4];
            acc[t] += w.x * xv.x + w.y * xv.y + w.z * xv.z + w.w * xv.w;
        }
    }
    float bias = pb[tid];
#pragma unroll
    for (int t = 0; t < 8; t++) {
        int m = m0 + t;
        int b = m >> 10, tt = m & 1023;
        float msk = (tt < lens[b]) ? 1.0f : 0.0f;
        float val = (acc[t] + bias) * msk;
        if (tid < NOUT) om[((size_t)b * NOUT + tid) * TD + tt] = val;
        else            ol[((size_t)b * NOUT + (tid - NOUT)) * TD + tt] = val;
    }
}

// ---------------- launch ----------------
extern "C" void kernel_launch(void* const* d_in, const int* in_sizes, int n_in,
                              void* d_out, int out_size) {
    const float* emb  = (const float*)d_in[0];
    const float* Wq   = (const float*)d_in[1];
    const float* Wk   = (const float*)d_in[2];
    const float* Wv   = (const float*)d_in[3];
    const float* Wo   = (const float*)d_in[4];
    const float* bq   = (const float*)d_in[5];
    const float* bk   = (const float*)d_in[6];
    const float* bv   = (const float*)d_in[7];
    const float* bo   = (const float*)d_in[8];
    const float* relk = (const float*)d_in[9];
    const float* relv = (const float*)d_in[10];
    const float* ln1g = (const float*)d_in[11];
    const float* ln1b = (const float*)d_in[12];
    const float* ln2g = (const float*)d_in[13];
    const float* ln2b = (const float*)d_in[14];
    const float* fw1  = (const float*)d_in[15];
    const float* fb1  = (const float*)d_in[16];
    const float* fw2  = (const float*)d_in[17];
    const float* fb2  = (const float*)d_in[18];
    const float* pw   = (const float*)d_in[19];
    const float* pb   = (const float*)d_in[20];
    const int*   tok  = (const int*)d_in[21];
    const int*   lens = (const int*)d_in[22];

    float* out      = (float*)d_out;
    float* out_x    = out;
    float* out_m    = out_x + (size_t)BD * CD * TD;
    float* out_logs = out_m + (size_t)BD * NOUT * TD;
    float* out_mask = out_logs + (size_t)BD * NOUT * TD;

    float *px, *pq, *pk, *pv, *pt, *pf;
    cudaGetSymbolAddress((void**)&px, g_x);
    cudaGetSymbolAddress((void**)&pq, g_q);
    cudaGetSymbolAddress((void**)&pk, g_k);
    cudaGetSymbolAddress((void**)&pv, g_v);
    cudaGetSymbolAddress((void**)&pt, g_t);
    cudaGetSymbolAddress((void**)&pf, g_f);

    cudaFuncSetAttribute(attn_kernel,
                         cudaFuncAttributeMaxDynamicSharedMemorySize, ATTN_SMEM);

    embed_kernel<<<MROWS * CD / 256, 256>>>(emb, tok);

    dim3 gQKV(CD / 64, MROWS / 128, 3);     // fused QKV: 768 blocks
    dim3 gC2(CD / 64, MROWS / 128, 2);      // split-K2 N=256 GEMMs: 512 blocks
    dim3 gF(FCD / 64, MROWS / 128);         // FFN1: 1024 blocks
    for (int i = 0; i < NL; i++) {
        const size_t wcc = (size_t)i * CD * CD;
        qkv_k<<<gQKV, 128>>>(px, Wq + wcc, Wk + wcc, Wv + wcc,
                             bq + i * CD, bk + i * CD, bv + i * CD, pq, pk, pv);
        attn_kernel<<<dim3(TD / QB, NH, BD), ATHR, ATTN_SMEM>>>(
            pq, pk, pv, relk + (size_t)i * 9 * HD_, relv + (size_t)i * 9 * HD_,
            lens, pt);
        // Wo: split-K2, partials in pq and pf (first 8M floats of g_f, dead here)
        sgemm_sk2<<<gC2, 128>>>(pt, Wo + wcc, bo + i * CD, pq, pf, CD, CD);
        add_ln3_kernel<<<MROWS / 8, 256>>>(px, pq, pf, ln1g + i * CD,
                                           ln1b + i * CD, px, lens, 0);
        sgemm_k<<<gF, 128>>>(px, fw1 + (size_t)i * CD * FCD, fb1 + i * FCD,
                             pf, FCD, CD, 1);
        // FFN2: split-K2, partials in pt and pq (both dead here)
        sgemm_sk2<<<gC2, 128>>>(pf, fw2 + (size_t)i * FCD * CD, fb2 + i * CD,
                                pt, pq, CD, FCD);
        add_ln3_kernel<<<MROWS / 8, 256>>>(px, pt, pq, ln2g + i * CD,
                                           ln2b + i * CD, px, lens, 1);
    }

    xout_kernel<<<dim3(TD / 32, CD / 32, BD), dim3(32, 8)>>>(px, out_x);
    maskout_kernel<<<BD * TD / 256, 256>>>(lens, out_mask);
    stats_kernel<<<MROWS / 8, 384>>>(px, pw, pb, lens, out_m, out_logs);
}

// round 10
// speedup vs baseline: 2.1558x; 2.1558x over previous
#include <cuda_runtime.h>
#include <cuda_bf16.h>

// Problem constants
#define MROWS 8192     // B*T
#define CD    256
#define FCD   1024
#define TD    1024
#define BD    8
#define HD_   64
#define NH    4
#define NL    6
#define NOUT  192
#define QB    16
#define ATHR  512

typedef unsigned long long ull;
typedef unsigned int u32;

// ---------------- f32x2 helpers (attention) --------------------------------
__device__ __forceinline__ ull pack2(float lo, float hi) {
    ull d;
    asm("mov.b64 %0, {%1, %2};" : "=l"(d) : "f"(lo), "f"(hi));
    return d;
}
__device__ __forceinline__ float2 unpack2(ull v) {
    float lo, hi;
    asm("mov.b64 {%0, %1}, %2;" : "=f"(lo), "=f"(hi) : "l"(v));
    return make_float2(lo, hi);
}
__device__ __forceinline__ void fma2(ull& d, ull a, ull b) {
    asm("fma.rn.f32x2 %0, %1, %2, %0;" : "+l"(d) : "l"(a), "l"(b));
}

// ---------------- mma.sync helpers -----------------------------------------
__device__ __forceinline__ u32 smem_u32(const void* p) {
    u32 a;
    asm("{ .reg .u64 t; cvta.to.shared.u64 t, %1; cvt.u32.u64 %0, t; }"
        : "=r"(a) : "l"(p));
    return a;
}
#define LDSM4(r, a) \
    asm volatile("ldmatrix.sync.aligned.m8n8.x4.shared.b16 {%0,%1,%2,%3}, [%4];" \
        : "=r"((r)[0]), "=r"((r)[1]), "=r"((r)[2]), "=r"((r)[3]) : "r"(a))
#define LDSM4T(r, a) \
    asm volatile("ldmatrix.sync.aligned.m8n8.x4.trans.shared.b16 {%0,%1,%2,%3}, [%4];" \
        : "=r"((r)[0]), "=r"((r)[1]), "=r"((r)[2]), "=r"((r)[3]) : "r"(a))

__device__ __forceinline__ void mma16816(float* c, const u32* a, const u32* b) {
    asm volatile(
        "mma.sync.aligned.m16n8k16.row.col.f32.bf16.bf16.f32 "
        "{%0,%1,%2,%3}, {%4,%5,%6,%7}, {%8,%9}, {%0,%1,%2,%3};"
        : "+f"(c[0]), "+f"(c[1]), "+f"(c[2]), "+f"(c[3])
        : "r"(a[0]), "r"(a[1]), "r"(a[2]), "r"(a[3]), "r"(b[0]), "r"(b[1]));
}

// hi/lo bf16 split of a float2 -> two packed u32
__device__ __forceinline__ void split2(float2 v, u32& hi, u32& lo) {
    __nv_bfloat162 h = __float22bfloat162_rn(v);
    float2 fh = __bfloat1622float2(h);
    __nv_bfloat162 l = __float22bfloat162_rn(make_float2(v.x - fh.x, v.y - fh.y));
    hi = *(u32*)&h;
    lo = *(u32*)&l;
}

// ---------------- scratch (device globals; no allocation allowed) ----------
__device__ float g_x[MROWS * CD];
__device__ float g_q[MROWS * CD];
__device__ float g_k[MROWS * CD];
__device__ float g_v[MROWS * CD];
__device__ float g_t[MROWS * CD];
__device__ float g_f[MROWS * FCD];

// ---------------- embedding ----------------
__global__ void embed_kernel(const float* __restrict__ emb,
                             const int* __restrict__ tok) {
    int idx = blockIdx.x * 256 + threadIdx.x;
    int m = idx >> 8;
    int c = idx & 255;
    g_x[idx] = emb[tok[m] * CD + c] * 16.0f;          // sqrt(256)
}

// ---------------- tensor-core GEMM: Y = A[MxK] @ W[KxN] + bias (opt relu) --
// block 128x128, 256 thr (8 warps, 2Mx4N), warp tile 64x32, K chunk 32.
// fp32 -> bf16 hi/lo; 3 mma passes => ~fp32 accuracy.
#define SA 40      // A smem stride (32 k + 8 pad), bf16 elems
#define SB 136     // B smem stride (128 n + 8 pad), bf16 elems

__device__ __forceinline__
void gemm_mma(const float* __restrict__ A, const float* __restrict__ W,
              const float* __restrict__ bias, float* __restrict__ Y,
              int N, int K, int relu)
{
    __shared__ __nv_bfloat16 Ahi[128 * SA], Alo[128 * SA];
    __shared__ __nv_bfloat16 Bhi[32 * SB],  Blo[32 * SB];

    int tid = threadIdx.x;                 // 256
    int lane = tid & 31, warp = tid >> 5;
    int wm = warp >> 2, wn = warp & 3;     // 2 x 4
    int rowBase = blockIdx.y * 128;
    int colBase = blockIdx.x * 128;

    float c[4][4][4];
#pragma unroll
    for (int mi = 0; mi < 4; mi++)
#pragma unroll
        for (int ni = 0; ni < 4; ni++)
#pragma unroll
            for (int j = 0; j < 4; j++) c[mi][ni][j] = 0.f;

    int arow = tid >> 1, akh = (tid & 1) * 16;     // A fill: row, k-half
    int brow = tid >> 3, bn0 = (tid & 7) * 16;     // B fill: k-row, n-quarter

    u32 aHiB = smem_u32(Ahi), aLoB = smem_u32(Alo);
    u32 bHiB = smem_u32(Bhi), bLoB = smem_u32(Blo);

    // ldmatrix lane addressing (element offsets)
    int aLdRow = lane & 15, aLdOff = (lane >> 4) << 3;
    int bLdRow = lane & 15, bLdOff = (lane >> 4) << 3;

    for (int kb = 0; kb < K; kb += 32) {
        // ---- A fill: 128x32 fp32 -> hi/lo bf16 ----
        {
            const float4* p = (const float4*)(A + (size_t)(rowBase + arow) * K + kb + akh);
            int base = arow * SA + akh;
#pragma unroll
            for (int i = 0; i < 4; i++) {
                float4 v = p[i];
                u32 h0, l0, h1, l1;
                split2(make_float2(v.x, v.y), h0, l0);
                split2(make_float2(v.z, v.w), h1, l1);
                *(u32*)&Ahi[base + i * 4]     = h0;
                *(u32*)&Ahi[base + i * 4 + 2] = h1;
                *(u32*)&Alo[base + i * 4]     = l0;
                *(u32*)&Alo[base + i * 4 + 2] = l1;
            }
        }
        // ---- B fill: 32x128 fp32 -> hi/lo bf16 ----
        {
            const float* q = W + (size_t)(kb + brow) * N + colBase + bn0;
            int base = brow * SB + bn0;
#pragma unroll
            for (int i = 0; i < 4; i++) {
                float4 v = *(const float4*)(q + i * 4);
                u32 h0, l0, h1, l1;
                split2(make_float2(v.x, v.y), h0, l0);
                split2(make_float2(v.z, v.w), h1, l1);
                *(u32*)&Bhi[base + i * 4]     = h0;
                *(u32*)&Bhi[base + i * 4 + 2] = h1;
                *(u32*)&Blo[base + i * 4]     = l0;
                *(u32*)&Blo[base + i * 4 + 2] = l1;
            }
        }
        __syncthreads();

        // ---- 2 k-steps of 16 ----
#pragma unroll
        for (int ks = 0; ks < 2; ks++) {
            int k0 = ks * 16;
            // B fragments: 4 n-tiles (2 x4.trans loads), hi and lo
            u32 bh[8], bl[8];
#pragma unroll
            for (int t = 0; t < 2; t++) {
                u32 off = (u32)(((k0 + bLdRow) * SB + wn * 32 + t * 16 + bLdOff) * 2);
                LDSM4T(&bh[t * 4], bHiB + off);
                LDSM4T(&bl[t * 4], bLoB + off);
            }
#pragma unroll
            for (int mi = 0; mi < 4; mi++) {
                u32 off = (u32)(((wm * 64 + mi * 16 + aLdRow) * SA + k0 + aLdOff) * 2);
                u32 ah[4], al[4];
                LDSM4(ah, aHiB + off);
                LDSM4(al, aLoB + off);
#pragma unroll
                for (int ni = 0; ni < 4; ni++) {
                    mma16816(c[mi][ni], ah, &bh[ni * 2]);
                    mma16816(c[mi][ni], al, &bh[ni * 2]);
                    mma16816(c[mi][ni], ah, &bl[ni * 2]);
                }
            }
        }
        __syncthreads();
    }

    // ---- epilogue ----
#pragma unroll
    for (int mi = 0; mi < 4; mi++) {
#pragma unroll
        for (int ni = 0; ni < 4; ni++) {
            int r0 = rowBase + wm * 64 + mi * 16 + (lane >> 2);
            int cc = colBase + wn * 32 + ni * 8 + (lane & 3) * 2;
            float2 bi = *(const float2*)&bias[cc];
            float2 o0 = make_float2(c[mi][ni][0] + bi.x, c[mi][ni][1] + bi.y);
            float2 o1 = make_float2(c[mi][ni][2] + bi.x, c[mi][ni][3] + bi.y);
            if (relu) {
                o0.x = fmaxf(o0.x, 0.f); o0.y = fmaxf(o0.y, 0.f);
                o1.x = fmaxf(o1.x, 0.f); o1.y = fmaxf(o1.y, 0.f);
            }
            *(float2*)&Y[(size_t)r0 * N + cc] = o0;
            *(float2*)&Y[(size_t)(r0 + 8) * N + cc] = o1;
        }
    }
}

__global__ __launch_bounds__(256, 2)
void tgemm(const float* __restrict__ A, const float* __restrict__ W,
           const float* __restrict__ bias, float* __restrict__ Y,
           int N, int K, int relu) {
    gemm_mma(A, W, bias, Y, N, K, relu);
}

__global__ __launch_bounds__(256, 2)
void qkv_tc(const float* __restrict__ A,
            const float* __restrict__ W0, const float* __restrict__ W1,
            const float* __restrict__ W2,
            const float* __restrict__ b0, const float* __restrict__ b1,
            const float* __restrict__ b2,
            float* __restrict__ Y0, float* __restrict__ Y1, float* __restrict__ Y2) {
    const float* W = (blockIdx.z == 0) ? W0 : (blockIdx.z == 1 ? W1 : W2);
    const float* bb = (blockIdx.z == 0) ? b0 : (blockIdx.z == 1 ? b1 : b2);
    float* Y = (blockIdx.z == 0) ? Y0 : (blockIdx.z == 1 ? Y1 : Y2);
    gemm_mma(A, W, bb, Y, CD, CD, 0);
}

// ---------------- fused attention (QB=16 queries per block, 512 thr) -------
#define ATTN_SMEM ((1024 + 192 + 256 + 16 + 160 + 16384) * 4)

__global__ __launch_bounds__(ATHR, 1)
void attn_kernel(const float* __restrict__ Q, const float* __restrict__ K,
                 const float* __restrict__ V, const float* __restrict__ relk,
                 const float* __restrict__ relv, const int* __restrict__ lens,
                 float* __restrict__ O) {
    extern __shared__ float sm[];
    float* sQ    = sm;
    float* sRelK = sQ + QB * HD_;
    float* sPart = sRelK + QB * 12;
    float* sInv  = sPart + 256;
    float* sDiag = sInv + 16;
    float* sS    = sDiag + 160;

    int tid = threadIdx.x;
    int q0 = blockIdx.x * QB;
    int h  = blockIdx.y;
    int b  = blockIdx.z;
    int len = lens[b];

    for (int i = tid; i < QB * HD_; i += ATHR) {
        int qq = i >> 6, d = i & 63;
        sQ[i] = Q[((size_t)(b * TD + q0 + qq) * CD) + h * HD_ + d] * 0.125f;
    }
    __syncthreads();

    if (tid < QB * 9) {
        int qq = tid / 9, r = tid % 9;
        const float* rw = relk + r * HD_;
        float s = 0.f;
#pragma unroll
        for (int d = 0; d < HD_; d++) s += sQ[qq * HD_ + d] * rw[d];
        sRelK[qq * 12 + r] = s;
    }
    __syncthreads();

    {
        const float* Kb = K + (size_t)b * TD * CD + h * HD_;
        ull acc[2][QB];
#pragma unroll
        for (int g = 0; g < 2; g++)
#pragma unroll
            for (int qq = 0; qq < QB; qq++) acc[g][qq] = 0ull;

        const float* kp0 = Kb + (size_t)tid * CD;
        const float* kp1 = Kb + (size_t)(tid + 512) * CD;
#pragma unroll 4
        for (int d4 = 0; d4 < 16; d4++) {
            ulonglong2 kv0 = *(const ulonglong2*)(kp0 + d4 * 4);
            ulonglong2 kv1 = *(const ulonglong2*)(kp1 + d4 * 4);
#pragma unroll
            for (int qq = 0; qq < QB; qq++) {
                ull qp0 = *(const ull*)&sQ[qq * HD_ + d4 * 4];
                ull qp1 = *(const ull*)&sQ[qq * HD_ + d4 * 4 + 2];
                fma2(acc[0][qq], qp0, kv0.x);
                fma2(acc[0][qq], qp1, kv0.y);
                fma2(acc[1][qq], qp0, kv1.x);
                fma2(acc[1][qq], qp1, kv1.y);
            }
        }

        float psum[QB];
#pragma unroll
        for (int qq = 0; qq < QB; qq++) psum[qq] = 0.f;
#pragma unroll
        for (int g = 0; g < 2; g++) {
            int key = tid + g * 512;
            bool kok = key < len;
#pragma unroll
            for (int qq = 0; qq < QB; qq++) {
                float2 u = unpack2(acc[g][qq]);
                float s = u.x + u.y;
                int r = key - (q0 + qq) + 4;
                if ((unsigned)r <= 8u) s += sRelK[qq * 12 + r];
                float e = (kok && (q0 + qq) < len) ? __expf(s) : 0.f;
                sS[qq * TD + key] = e;
                psum[qq] += e;
            }
        }
        int lane = tid & 31, warp = tid >> 5;
#pragma unroll
        for (int qq = 0; qq < QB; qq++) {
            float v = psum[qq];
#pragma unroll
            for (int off = 16; off > 0; off >>= 1)
                v += __shfl_xor_sync(0xffffffffu, v, off);
            if (lane == 0) sPart[qq * 16 + warp] = v;
        }
    }
    __syncthreads();

    if (tid < QB) {
        float s = 0.f;
#pragma unroll
        for (int w = 0; w < 16; w++) s += sPart[tid * 16 + w];
        sInv[tid] = (s > 0.f) ? 1.0f / s : 0.f;
    }
    if (tid >= 64 && tid < 64 + QB * 9) {
        int t2 = tid - 64;
        int qq = t2 / 9, r = t2 % 9;
        int k = q0 + qq + r - 4;
        sDiag[qq * 9 + r] = (k >= 0 && k < TD) ? sS[qq * TD + k] : 0.f;
    }
    __syncthreads();

    {
        int grp = tid >> 5, lane = tid & 31;
        const float* Vb = V + (size_t)b * TD * CD + h * HD_ + lane * 2;
        ull acc[QB];
#pragma unroll
        for (int qq = 0; qq < QB; qq++) acc[qq] = 0ull;
        int kbase = grp * 64;
#pragma unroll 2
        for (int kk = 0; kk < 64; kk++) {
            int key = kbase + kk;
            ull vv = *(const ull*)(Vb + (size_t)key * CD);
#pragma unroll
            for (int qq = 0; qq < QB; qq++) {
                float p = sS[qq * TD + key];
                fma2(acc[qq], pack2(p, p), vv);
            }
        }
        __syncthreads();
#pragma unroll
        for (int qq = 0; qq < QB; qq++)
            *(ull*)&sS[(grp * 16 + qq) * 64 + lane * 2] = acc[qq];
    }
    __syncthreads();

    for (int i = tid; i < QB * HD_; i += ATHR) {
        int qq = i >> 6, dd = i & 63;
        float a = 0.f;
#pragma unroll
        for (int g = 0; g < 16; g++) a += sS[(g * 16 + qq) * 64 + dd];
        float inv = sInv[qq];
        a *= inv;
#pragma unroll
        for (int r = 0; r < 9; r++)
            a += sDiag[qq * 9 + r] * inv * relv[r * HD_ + dd];
        O[((size_t)(b * TD + q0 + qq) * CD) + h * HD_ + dd] = a;
    }
}

// ---------------- residual add + LayerNorm: warp per row -------------------
__global__ __launch_bounds__(256)
void add_ln_kernel(const float* __restrict__ a, const float* __restrict__ r,
                   const float* __restrict__ g, const float* __restrict__ bb,
                   float* __restrict__ o, const int* __restrict__ lens,
                   int domask) {
    int warp = threadIdx.x >> 5, lane = threadIdx.x & 31;
    int m = blockIdx.x * 8 + warp;
    const float4* a4 = (const float4*)(a + (size_t)m * CD);
    const float4* r4 = (const float4*)(r + (size_t)m * CD);
    float4 v0 = a4[lane * 2], v1 = a4[lane * 2 + 1];
    float4 w0 = r4[lane * 2], w1 = r4[lane * 2 + 1];
    v0.x += w0.x; v0.y += w0.y; v0.z += w0.z; v0.w += w0.w;
    v1.x += w1.x; v1.y += w1.y; v1.z += w1.z; v1.w += w1.w;
    float s = v0.x + v0.y + v0.z + v0.w + v1.x + v1.y + v1.z + v1.w;
    float q = v0.x * v0.x + v0.y * v0.y + v0.z * v0.z + v0.w * v0.w +
              v1.x * v1.x + v1.y * v1.y + v1.z * v1.z + v1.w * v1.w;
#pragma unroll
    for (int off = 16; off > 0; off >>= 1) {
        s += __shfl_xor_sync(0xffffffffu, s, off);
        q += __shfl_xor_sync(0xffffffffu, q, off);
    }
    float mean = s * (1.0f / CD);
    float var = q * (1.0f / CD) - mean * mean;
    float inv = rsqrtf(var + 1e-5f);
    float4 g0 = ((const float4*)g)[lane * 2], g1 = ((const float4*)g)[lane * 2 + 1];
    float4 b0 = ((const float4*)bb)[lane * 2], b1 = ((const float4*)bb)[lane * 2 + 1];
    float4 o0, o1;
    o0.x = (v0.x - mean) * inv * g0.x + b0.x;
    o0.y = (v0.y - mean) * inv * g0.y + b0.y;
    o0.z = (v0.z - mean) * inv * g0.z + b0.z;
    o0.w = (v0.w - mean) * inv * g0.w + b0.w;
    o1.x = (v1.x - mean) * inv * g1.x + b1.x;
    o1.y = (v1.y - mean) * inv * g1.y + b1.y;
    o1.z = (v1.z - mean) * inv * g1.z + b1.z;
    o1.w = (v1.w - mean) * inv * g1.w + b1.w;
    if (domask) {
        int bb2 = m >> 10, t = m & 1023;
        if (t >= lens[bb2]) {
            o0 = make_float4(0.f, 0.f, 0.f, 0.f);
            o1 = make_float4(0.f, 0.f, 0.f, 0.f);
        }
    }
    ((float4*)(o + (size_t)m * CD))[lane * 2] = o0;
    ((float4*)(o + (size_t)m * CD))[lane * 2 + 1] = o1;
}

// ---------------- outputs ----------------
__global__ void xout_kernel(const float* __restrict__ x, float* __restrict__ ox) {
    __shared__ float tile[32][33];
    int t0 = blockIdx.x * 32, c0 = blockIdx.y * 32, b = blockIdx.z;
    int tx = threadIdx.x, ty = threadIdx.y;
    for (int i = ty; i < 32; i += 8)
        tile[i][tx] = x[((size_t)(b * TD + t0 + i) * CD) + c0 + tx];
    __syncthreads();
    for (int i = ty; i < 32; i += 8)
        ox[((size_t)(b * CD + c0 + i) * TD) + t0 + tx] = tile[tx][i];
}

__global__ void maskout_kernel(const int* __restrict__ lens, float* __restrict__ om) {
    int idx = blockIdx.x * 256 + threadIdx.x;
    int b = idx >> 10, t = idx & 1023;
    om[idx] = (t < lens[b]) ? 1.0f : 0.0f;
}

__global__ __launch_bounds__(384)
void stats_kernel(const float* __restrict__ x, const float* __restrict__ pw,
                  const float* __restrict__ pb, const int* __restrict__ lens,
                  float* __restrict__ om, float* __restrict__ ol) {
    int m0 = blockIdx.x * 8;
    __shared__ float sx[8][CD];
    int tid = threadIdx.x;
    for (int i = tid; i < 8 * CD / 4; i += 384)
        ((float4*)sx)[i] = ((const float4*)(x + (size_t)m0 * CD))[i];
    __syncthreads();

    float acc[8];
#pragma unroll
    for (int t = 0; t < 8; t++) acc[t] = 0.f;
    const float4* w4 = (const float4*)(pw + (size_t)tid * CD);
#pragma unroll 8
    for (int i = 0; i < CD / 4; i++) {
        float4 w = w4[i];
#pragma unroll
        for (int t = 0; t < 8; t++) {
            float4 xv = *(const float4*)&sx[t][i * 4];
            acc[t] += w.x * xv.x + w.y * xv.y + w.z * xv.z + w.w * xv.w;
        }
    }
    float bias = pb[tid];
#pragma unroll
    for (int t = 0; t < 8; t++) {
        int m = m0 + t;
        int b = m >> 10, tt = m & 1023;
        float msk = (tt < lens[b]) ? 1.0f : 0.0f;
        float val = (acc[t] + bias) * msk;
        if (tid < NOUT) om[((size_t)b * NOUT + tid) * TD + tt] = val;
        else            ol[((size_t)b * NOUT + (tid - NOUT)) * TD + tt] = val;
    }
}

// ---------------- launch ----------------
extern "C" void kernel_launch(void* const* d_in, const int* in_sizes, int n_in,
                              void* d_out, int out_size) {
    const float* emb  = (const float*)d_in[0];
    const float* Wq   = (const float*)d_in[1];
    const float* Wk   = (const float*)d_in[2];
    const float* Wv   = (const float*)d_in[3];
    const float* Wo   = (const float*)d_in[4];
    const float* bq   = (const float*)d_in[5];
    const float* bk   = (const float*)d_in[6];
    const float* bv   = (const float*)d_in[7];
    const float* bo   = (const float*)d_in[8];
    const float* relk = (const float*)d_in[9];
    const float* relv = (const float*)d_in[10];
    const float* ln1g = (const float*)d_in[11];
    const float* ln1b = (const float*)d_in[12];
    const float* ln2g = (const float*)d_in[13];
    const float* ln2b = (const float*)d_in[14];
    const float* fw1  = (const float*)d_in[15];
    const float* fb1  = (const float*)d_in[16];
    const float* fw2  = (const float*)d_in[17];
    const float* fb2  = (const float*)d_in[18];
    const float* pw   = (const float*)d_in[19];
    const float* pb   = (const float*)d_in[20];
    const int*   tok  = (const int*)d_in[21];
    const int*   lens = (const int*)d_in[22];

    float* out      = (float*)d_out;
    float* out_x    = out;
    float* out_m    = out_x + (size_t)BD * CD * TD;
    float* out_logs = out_m + (size_t)BD * NOUT * TD;
    float* out_mask = out_logs + (size_t)BD * NOUT * TD;

    float *px, *pq, *pk, *pv, *pt, *pf;
    cudaGetSymbolAddress((void**)&px, g_x);
    cudaGetSymbolAddress((void**)&pq, g_q);
    cudaGetSymbolAddress((void**)&pk, g_k);
    cudaGetSymbolAddress((void**)&pv, g_v);
    cudaGetSymbolAddress((void**)&pt, g_t);
    cudaGetSymbolAddress((void**)&pf, g_f);

    cudaFuncSetAttribute(attn_kernel,
                         cudaFuncAttributeMaxDynamicSharedMemorySize, ATTN_SMEM);

    embed_kernel<<<MROWS * CD / 256, 256>>>(emb, tok);

    dim3 gQKV(CD / 128, MROWS / 128, 3);   // 384 blocks
    dim3 gC(CD / 128, MROWS / 128);        // 128 blocks
    dim3 gF(FCD / 128, MROWS / 128);       // 512 blocks
    for (int i = 0; i < NL; i++) {
        const size_t wcc = (size_t)i * CD * CD;
        qkv_tc<<<gQKV, 256>>>(px, Wq + wcc, Wk + wcc, Wv + wcc,
                              bq + i * CD, bk + i * CD, bv + i * CD,
                              pq, pk, pv);
        attn_kernel<<<dim3(TD / QB, NH, BD), ATHR, ATTN_SMEM>>>(
            pq, pk, pv, relk + (size_t)i * 9 * HD_, relv + (size_t)i * 9 * HD_,
            lens, pt);
        tgemm<<<gC, 256>>>(pt, Wo + wcc, bo + i * CD, pq, CD, CD, 0);
        add_ln_kernel<<<MROWS / 8, 256>>>(px, pq, ln1g + i * CD, ln1b + i * CD,
                                          px, lens, 0);
        tgemm<<<gF, 256>>>(px, fw1 + (size_t)i * CD * FCD, fb1 + i * FCD,
                           pf, FCD, CD, 1);
        tgemm<<<gC, 256>>>(pf, fw2 + (size_t)i * FCD * CD, fb2 + i * CD,
                           pt, CD, FCD, 0);
        add_ln_kernel<<<MROWS / 8, 256>>>(px, pt, ln2g + i * CD, ln2b + i * CD,
                                          px, lens, 1);
    }

    xout_kernel<<<dim3(TD / 32, CD / 32, BD), dim3(32, 8)>>>(px, out_x);
    maskout_kernel<<<BD * TD / 256, 256>>>(lens, out_mask);
    stats_kernel<<<MROWS / 8, 384>>>(px, pw, pb, lens, out_m, out_logs);
}

// round 11
// speedup vs baseline: 2.3045x; 1.0690x over previous
#include <cuda_runtime.h>
#include <cuda_bf16.h>

// Problem constants
#define MROWS 8192     // B*T
#define CD    256
#define FCD   1024
#define TD    1024
#define BD    8
#define HD_   64
#define NH    4
#define NL    6
#define NOUT  192
#define QB    16

typedef unsigned long long ull;
typedef unsigned int u32;
typedef unsigned short u16;

// ---------------- mma.sync helpers -----------------------------------------
__device__ __forceinline__ void mma16816(float* c, const u32* a, const u32* b) {
    asm("mma.sync.aligned.m16n8k16.row.col.f32.bf16.bf16.f32 "
        "{%0,%1,%2,%3}, {%4,%5,%6,%7}, {%8,%9}, {%0,%1,%2,%3};"
        : "+f"(c[0]), "+f"(c[1]), "+f"(c[2]), "+f"(c[3])
        : "r"(a[0]), "r"(a[1]), "r"(a[2]), "r"(a[3]), "r"(b[0]), "r"(b[1]));
}
#define LDSM4(r, a) \
    asm volatile("ldmatrix.sync.aligned.m8n8.x4.shared.b16 {%0,%1,%2,%3}, [%4];" \
        : "=r"((r)[0]), "=r"((r)[1]), "=r"((r)[2]), "=r"((r)[3]) : "r"(a))
#define LDSM4T(r, a) \
    asm volatile("ldmatrix.sync.aligned.m8n8.x4.trans.shared.b16 {%0,%1,%2,%3}, [%4];" \
        : "=r"((r)[0]), "=r"((r)[1]), "=r"((r)[2]), "=r"((r)[3]) : "r"(a))

__device__ __forceinline__ u32 smem_u32(const void* p) {
    u32 a;
    asm("{ .reg .u64 t; cvta.to.shared.u64 t, %1; cvt.u32.u64 %0, t; }"
        : "=r"(a) : "l"(p));
    return a;
}

// hi/lo bf16 split of a float2 -> two packed u32
__device__ __forceinline__ void split2(float2 v, u32& hi, u32& lo) {
    __nv_bfloat162 h = __float22bfloat162_rn(v);
    float2 fh = __bfloat1622float2(h);
    __nv_bfloat162 l = __float22bfloat162_rn(make_float2(v.x - fh.x, v.y - fh.y));
    hi = *(u32*)&h;
    lo = *(u32*)&l;
}

// ---------------- scratch (device globals; no allocation allowed) ----------
__device__ float g_x[MROWS * CD];
__device__ float g_q[MROWS * CD];
__device__ float g_k[MROWS * CD];
__device__ float g_v[MROWS * CD];
__device__ float g_t[MROWS * CD];
__device__ float g_f[MROWS * FCD];
__device__ u16 g_khi[MROWS * CD], g_klo[MROWS * CD];     // K bf16 hi/lo [tok][c]
__device__ u16 g_vthi[MROWS * CD], g_vtlo[MROWS * CD];   // V^T bf16 [b][c][t]

// ---------------- embedding ----------------
__global__ void embed_kernel(const float* __restrict__ emb,
                             const int* __restrict__ tok) {
    int idx = blockIdx.x * 256 + threadIdx.x;
    int m = idx >> 8;
    int c = idx & 255;
    g_x[idx] = emb[tok[m] * CD + c] * 16.0f;          // sqrt(256)
}

// ---------------- K convert: f32 -> bf16 hi/lo -----------------------------
__global__ void kcvt_kernel(const float* __restrict__ src) {
    int idx = blockIdx.x * 256 + threadIdx.x;          // over MROWS*CD/2
    float2 v = ((const float2*)src)[idx];
    u32 h, l;
    split2(v, h, l);
    ((u32*)g_khi)[idx] = h;
    ((u32*)g_klo)[idx] = l;
}

// ---------------- V transpose: f32 [b*T][C] -> bf16 [b][C][T] hi/lo --------
__global__ void vtrans_kernel(const float* __restrict__ v) {
    __shared__ float tile[32][33];
    int t0 = blockIdx.x * 32, c0 = blockIdx.y * 32, b = blockIdx.z;
    int tx = threadIdx.x, ty = threadIdx.y;            // 32 x 8
    for (int i = ty; i < 32; i += 8)
        tile[i][tx] = v[(size_t)(b * TD + t0 + i) * CD + c0 + tx];
    __syncthreads();
    for (int i = ty; i < 32; i += 8) {
        float x = tile[tx][i];
        __nv_bfloat16 h = __float2bfloat16(x);
        __nv_bfloat16 l = __float2bfloat16(x - __bfloat162float(h));
        size_t o = (size_t)(b * CD + c0 + i) * TD + t0 + tx;
        g_vthi[o] = *(u16*)&h;
        g_vtlo[o] = *(u16*)&l;
    }
}

// ---------------- tensor-core GEMM (unchanged from R10 winner) -------------
#define SA 40
#define SB 136

__device__ __forceinline__
void gemm_mma(const float* __restrict__ A, const float* __restrict__ W,
              const float* __restrict__ bias, float* __restrict__ Y,
              int N, int K, int relu)
{
    __shared__ __nv_bfloat16 Ahi[128 * SA], Alo[128 * SA];
    __shared__ __nv_bfloat16 Bhi[32 * SB],  Blo[32 * SB];

    int tid = threadIdx.x;
    int lane = tid & 31, warp = tid >> 5;
    int wm = warp >> 2, wn = warp & 3;
    int rowBase = blockIdx.y * 128;
    int colBase = blockIdx.x * 128;

    float c[4][4][4];
#pragma unroll
    for (int mi = 0; mi < 4; mi++)
#pragma unroll
        for (int ni = 0; ni < 4; ni++)
#pragma unroll
            for (int j = 0; j < 4; j++) c[mi][ni][j] = 0.f;

    int arow = tid >> 1, akh = (tid & 1) * 16;
    int brow = tid >> 3, bn0 = (tid & 7) * 16;

    u32 aHiB = smem_u32(Ahi), aLoB = smem_u32(Alo);
    u32 bHiB = smem_u32(Bhi), bLoB = smem_u32(Blo);
    int aLdRow = lane & 15, aLdOff = (lane >> 4) << 3;
    int bLdRow = lane & 15, bLdOff = (lane >> 4) << 3;

    for (int kb = 0; kb < K; kb += 32) {
        {
            const float4* p = (const float4*)(A + (size_t)(rowBase + arow) * K + kb + akh);
            int base = arow * SA + akh;
#pragma unroll
            for (int i = 0; i < 4; i++) {
                float4 v = p[i];
                u32 h0, l0, h1, l1;
                split2(make_float2(v.x, v.y), h0, l0);
                split2(make_float2(v.z, v.w), h1, l1);
                *(u32*)&Ahi[base + i * 4]     = h0;
                *(u32*)&Ahi[base + i * 4 + 2] = h1;
                *(u32*)&Alo[base + i * 4]     = l0;
                *(u32*)&Alo[base + i * 4 + 2] = l1;
            }
        }
        {
            const float* q = W + (size_t)(kb + brow) * N + colBase + bn0;
            int base = brow * SB + bn0;
#pragma unroll
            for (int i = 0; i < 4; i++) {
                float4 v = *(const float4*)(q + i * 4);
                u32 h0, l0, h1, l1;
                split2(make_float2(v.x, v.y), h0, l0);
                split2(make_float2(v.z, v.w), h1, l1);
                *(u32*)&Bhi[base + i * 4]     = h0;
                *(u32*)&Bhi[base + i * 4 + 2] = h1;
                *(u32*)&Blo[base + i * 4]     = l0;
                *(u32*)&Blo[base + i * 4 + 2] = l1;
            }
        }
        __syncthreads();

#pragma unroll
        for (int ks = 0; ks < 2; ks++) {
            int k0 = ks * 16;
            u32 bh[8], bl[8];
#pragma unroll
            for (int t = 0; t < 2; t++) {
                u32 off = (u32)(((k0 + bLdRow) * SB + wn * 32 + t * 16 + bLdOff) * 2);
                LDSM4T(&bh[t * 4], bHiB + off);
                LDSM4T(&bl[t * 4], bLoB + off);
            }
#pragma unroll
            for (int mi = 0; mi < 4; mi++) {
                u32 off = (u32)(((wm * 64 + mi * 16 + aLdRow) * SA + k0 + aLdOff) * 2);
                u32 ah[4], al[4];
                LDSM4(ah, aHiB + off);
                LDSM4(al, aLoB + off);
#pragma unroll
                for (int ni = 0; ni < 4; ni++) {
                    mma16816(c[mi][ni], ah, &bh[ni * 2]);
                    mma16816(c[mi][ni], al, &bh[ni * 2]);
                    mma16816(c[mi][ni], ah, &bl[ni * 2]);
                }
            }
        }
        __syncthreads();
    }

#pragma unroll
    for (int mi = 0; mi < 4; mi++) {
#pragma unroll
        for (int ni = 0; ni < 4; ni++) {
            int r0 = rowBase + wm * 64 + mi * 16 + (lane >> 2);
            int cc = colBase + wn * 32 + ni * 8 + (lane & 3) * 2;
            float2 bi = *(const float2*)&bias[cc];
            float2 o0 = make_float2(c[mi][ni][0] + bi.x, c[mi][ni][1] + bi.y);
            float2 o1 = make_float2(c[mi][ni][2] + bi.x, c[mi][ni][3] + bi.y);
            if (relu) {
                o0.x = fmaxf(o0.x, 0.f); o0.y = fmaxf(o0.y, 0.f);
                o1.x = fmaxf(o1.x, 0.f); o1.y = fmaxf(o1.y, 0.f);
            }
            *(float2*)&Y[(size_t)r0 * N + cc] = o0;
            *(float2*)&Y[(size_t)(r0 + 8) * N + cc] = o1;
        }
    }
}

__global__ __launch_bounds__(256, 2)
void tgemm(const float* __restrict__ A, const float* __restrict__ W,
           const float* __restrict__ bias, float* __restrict__ Y,
           int N, int K, int relu) {
    gemm_mma(A, W, bias, Y, N, K, relu);
}

__global__ __launch_bounds__(256, 2)
void qkv_tc(const float* __restrict__ A,
            const float* __restrict__ W0, const float* __restrict__ W1,
            const float* __restrict__ W2,
            const float* __restrict__ b0, const float* __restrict__ b1,
            const float* __restrict__ b2,
            float* __restrict__ Y0, float* __restrict__ Y1, float* __restrict__ Y2) {
    const float* W = (blockIdx.z == 0) ? W0 : (blockIdx.z == 1 ? W1 : W2);
    const float* bb = (blockIdx.z == 0) ? b0 : (blockIdx.z == 1 ? b1 : b2);
    float* Y = (blockIdx.z == 0) ? Y0 : (blockIdx.z == 1 ? Y1 : Y2);
    gemm_mma(A, W, bb, Y, CD, CD, 0);
}

// ---------------- tensor-core attention ------------------------------------
// 512 thr = 16 warps; warp w owns keys [w*64, w*64+64). QB=16 queries/block.
// smem floats: sQ 1024 | sRelK 192 | sPart 256 | sInv 16 | sDiag 160 | sAcc 16384
#define ATTN_SMEM ((1024 + 192 + 256 + 16 + 160 + 16384) * 4)

__global__ __launch_bounds__(512, 1)
void attn_tc(const float* __restrict__ Q,
             const u16* __restrict__ Khi, const u16* __restrict__ Klo,
             const u16* __restrict__ Vthi, const u16* __restrict__ Vtlo,
             const float* __restrict__ relk, const float* __restrict__ relv,
             const int* __restrict__ lens, float* __restrict__ O) {
    extern __shared__ float sm[];
    float* sQ    = sm;                    // 16*64
    float* sRelK = sQ + QB * HD_;         // 16*12
    float* sPart = sRelK + QB * 12;       // 16*16
    float* sInv  = sPart + 256;           // 16
    float* sDiag = sInv + 16;             // 16*9 (pad 160)
    float* sAcc  = sDiag + 160;           // 16 warps * 16 q * 64 d

    int tid = threadIdx.x;
    int lane = tid & 31, w = tid >> 5;
    int gid = lane >> 2, tid4 = lane & 3;
    int q0 = blockIdx.x * QB;
    int h  = blockIdx.y;
    int b  = blockIdx.z;
    int len = lens[b];

    // Q (scaled) to smem
    for (int i = tid; i < QB * HD_; i += 512) {
        int qq = i >> 6, d = i & 63;
        sQ[i] = Q[((size_t)(b * TD + q0 + qq) * CD) + h * HD_ + d] * 0.125f;
    }
    if (tid < 160) sDiag[tid] = 0.f;
    __syncthreads();

    // q . rel_k diagonals
    if (tid < QB * 9) {
        int qq = tid / 9, r = tid % 9;
        const float* rw = relk + r * HD_;
        float s = 0.f;
#pragma unroll
        for (int d = 0; d < HD_; d++) s += sQ[qq * HD_ + d] * rw[d];
        sRelK[qq * 12 + r] = s;
    }
    __syncthreads();

    // P fragments (built in QK epilogue, consumed by PV)
    u32 pah[4][4], pal[4][4];
    float psA, psB;
    {
        // Q fragments hi/lo from sQ
        u32 qh[4][4], ql[4][4];
#pragma unroll
        for (int ks = 0; ks < 4; ks++) {
            int c0 = ks * 16 + tid4 * 2;
            split2(*(float2*)&sQ[gid * 64 + c0],            qh[ks][0], ql[ks][0]);
            split2(*(float2*)&sQ[(gid + 8) * 64 + c0],      qh[ks][1], ql[ks][1]);
            split2(*(float2*)&sQ[gid * 64 + c0 + 8],        qh[ks][2], ql[ks][2]);
            split2(*(float2*)&sQ[(gid + 8) * 64 + c0 + 8],  qh[ks][3], ql[ks][3]);
        }

        float c[8][4];
#pragma unroll
        for (int nt = 0; nt < 8; nt++)
#pragma unroll
            for (int j = 0; j < 4; j++) c[nt][j] = 0.f;

        int keyB = w * 64 + gid;     // B-frag key row for this lane
        size_t kbase = ((size_t)(b * TD) + keyB) * CD + h * HD_;
#pragma unroll
        for (int ks = 0; ks < 4; ks++) {
            int dco = ks * 16 + tid4 * 2;
#pragma unroll
            for (int nt = 0; nt < 8; nt++) {
                size_t adr = kbase + (size_t)nt * 8 * CD + dco;
                u32 bf[2], blo[2];
                bf[0]  = *(const u32*)&Khi[adr];
                bf[1]  = *(const u32*)&Khi[adr + 8];
                blo[0] = *(const u32*)&Klo[adr];
                blo[1] = *(const u32*)&Klo[adr + 8];
                mma16816(c[nt], qh[ks], bf);
                mma16816(c[nt], ql[ks], bf);
                mma16816(c[nt], qh[ks], blo);
            }
        }

        // epilogue: bias + mask + exp, psums, diagonals, P fragments
        psA = 0.f; psB = 0.f;
        int qA = q0 + gid, qBq = q0 + gid + 8;
        bool qokA = qA < len, qokB = qBq < len;
#pragma unroll
        for (int nt = 0; nt < 8; nt++) {
            int k0 = w * 64 + nt * 8 + tid4 * 2;
            int k1 = k0 + 1;
            bool kok0 = k0 < len, kok1 = k1 < len;
            float e0 = c[nt][0], e1 = c[nt][1], e2 = c[nt][2], e3 = c[nt][3];
            int r0A = k0 - qA + 4, r1A = k1 - qA + 4;
            int r0B = k0 - qBq + 4, r1B = k1 - qBq + 4;
            if ((unsigned)r0A <= 8u) e0 += sRelK[gid * 12 + r0A];
            if ((unsigned)r1A <= 8u) e1 += sRelK[gid * 12 + r1A];
            if ((unsigned)r0B <= 8u) e2 += sRelK[(gid + 8) * 12 + r0B];
            if ((unsigned)r1B <= 8u) e3 += sRelK[(gid + 8) * 12 + r1B];
            e0 = (qokA && kok0) ? __expf(e0) : 0.f;
            e1 = (qokA && kok1) ? __expf(e1) : 0.f;
            e2 = (qokB && kok0) ? __expf(e2) : 0.f;
            e3 = (qokB && kok1) ? __expf(e3) : 0.f;
            psA += e0 + e1;
            psB += e2 + e3;
            if ((unsigned)r0A <= 8u) sDiag[gid * 9 + r0A] = e0;
            if ((unsigned)r1A <= 8u) sDiag[gid * 9 + r1A] = e1;
            if ((unsigned)r0B <= 8u) sDiag[(gid + 8) * 9 + r0B] = e2;
            if ((unsigned)r1B <= 8u) sDiag[(gid + 8) * 9 + r1B] = e3;
            int ks2 = nt >> 1;
            int half = (nt & 1) * 2;
            split2(make_float2(e0, e1), pah[ks2][half],     pal[ks2][half]);
            split2(make_float2(e2, e3), pah[ks2][half + 1], pal[ks2][half + 1]);
        }
        // quad reduce psums (lanes sharing gid)
        psA += __shfl_xor_sync(0xffffffffu, psA, 1);
        psA += __shfl_xor_sync(0xffffffffu, psA, 2);
        psB += __shfl_xor_sync(0xffffffffu, psB, 1);
        psB += __shfl_xor_sync(0xffffffffu, psB, 2);
        if (tid4 == 0) {
            sPart[gid * 16 + w] = psA;
            sPart[(gid + 8) * 16 + w] = psB;
        }
    }
    __syncthreads();

    if (tid < QB) {
        float s = 0.f;
#pragma unroll
        for (int ww = 0; ww < 16; ww++) s += sPart[tid * 16 + ww];
        sInv[tid] = (s > 0.f) ? 1.0f / s : 0.f;
    }

    // ---- PV via mma: O_partial[16q][64d] per warp ----
    float o[8][4];
#pragma unroll
    for (int dt = 0; dt < 8; dt++)
#pragma unroll
        for (int j = 0; j < 4; j++) o[dt][j] = 0.f;

    {
        int dimB = h * HD_ + gid;     // B-frag dim row base offset uses +dt*8
        size_t vbase = ((size_t)(b * CD) + dimB) * TD + w * 64;
#pragma unroll
        for (int ks2 = 0; ks2 < 4; ks2++) {
            int ko = ks2 * 16 + tid4 * 2;
#pragma unroll
            for (int dt = 0; dt < 8; dt++) {
                size_t adr = vbase + (size_t)dt * 8 * TD + ko;
                u32 bf[2], blo[2];
                bf[0]  = *(const u32*)&Vthi[adr];
                bf[1]  = *(const u32*)&Vthi[adr + 8];
                blo[0] = *(const u32*)&Vtlo[adr];
                blo[1] = *(const u32*)&Vtlo[adr + 8];
                mma16816(o[dt], pah[ks2], bf);
                mma16816(o[dt], pal[ks2], bf);
                mma16816(o[dt], pah[ks2], blo);
            }
        }
    }
    // store partials
#pragma unroll
    for (int dt = 0; dt < 8; dt++) {
        *(float2*)&sAcc[((w * 16 + gid) * 64) + dt * 8 + tid4 * 2]     =
            make_float2(o[dt][0], o[dt][1]);
        *(float2*)&sAcc[((w * 16 + gid + 8) * 64) + dt * 8 + tid4 * 2] =
            make_float2(o[dt][2], o[dt][3]);
    }
    __syncthreads();

    // combine 16 warps + rel_v + write
    for (int i = tid; i < QB * HD_; i += 512) {
        int qq = i >> 6, dd = i & 63;
        float a = 0.f;
#pragma unroll
        for (int g = 0; g < 16; g++) a += sAcc[(g * 16 + qq) * 64 + dd];
        float inv = sInv[qq];
        a *= inv;
#pragma unroll
        for (int r = 0; r < 9; r++)
            a += sDiag[qq * 9 + r] * inv * relv[r * HD_ + dd];
        O[((size_t)(b * TD + q0 + qq) * CD) + h * HD_ + dd] = a;
    }
}

// ---------------- residual add + LayerNorm: warp per row -------------------
__global__ __launch_bounds__(256)
void add_ln_kernel(const float* __restrict__ a, const float* __restrict__ r,
                   const float* __restrict__ g, const float* __restrict__ bb,
                   float* __restrict__ o, const int* __restrict__ lens,
                   int domask) {
    int warp = threadIdx.x >> 5, lane = threadIdx.x & 31;
    int m = blockIdx.x * 8 + warp;
    const float4* a4 = (const float4*)(a + (size_t)m * CD);
    const float4* r4 = (const float4*)(r + (size_t)m * CD);
    float4 v0 = a4[lane * 2], v1 = a4[lane * 2 + 1];
    float4 w0 = r4[lane * 2], w1 = r4[lane * 2 + 1];
    v0.x += w0.x; v0.y += w0.y; v0.z += w0.z; v0.w += w0.w;
    v1.x += w1.x; v1.y += w1.y; v1.z += w1.z; v1.w += w1.w;
    float s = v0.x + v0.y + v0.z + v0.w + v1.x + v1.y + v1.z + v1.w;
    float q = v0.x * v0.x + v0.y * v0.y + v0.z * v0.z + v0.w * v0.w +
              v1.x * v1.x + v1.y * v1.y + v1.z * v1.z + v1.w * v1.w;
#pragma unroll
    for (int off = 16; off > 0; off >>= 1) {
        s += __shfl_xor_sync(0xffffffffu, s, off);
        q += __shfl_xor_sync(0xffffffffu, q, off);
    }
    float mean = s * (1.0f / CD);
    float var = q * (1.0f / CD) - mean * mean;
    float inv = rsqrtf(var + 1e-5f);
    float4 g0 = ((const float4*)g)[lane * 2], g1 = ((const float4*)g)[lane * 2 + 1];
    float4 b0 = ((const float4*)bb)[lane * 2], b1 = ((const float4*)bb)[lane * 2 + 1];
    float4 o0, o1;
    o0.x = (v0.x - mean) * inv * g0.x + b0.x;
    o0.y = (v0.y - mean) * inv * g0.y + b0.y;
    o0.z = (v0.z - mean) * inv * g0.z + b0.z;
    o0.w = (v0.w - mean) * inv * g0.w + b0.w;
    o1.x = (v1.x - mean) * inv * g1.x + b1.x;
    o1.y = (v1.y - mean) * inv * g1.y + b1.y;
    o1.z = (v1.z - mean) * inv * g1.z + b1.z;
    o1.w = (v1.w - mean) * inv * g1.w + b1.w;
    if (domask) {
        int bb2 = m >> 10, t = m & 1023;
        if (t >= lens[bb2]) {
            o0 = make_float4(0.f, 0.f, 0.f, 0.f);
            o1 = make_float4(0.f, 0.f, 0.f, 0.f);
        }
    }
    ((float4*)(o + (size_t)m * CD))[lane * 2] = o0;
    ((float4*)(o + (size_t)m * CD))[lane * 2 + 1] = o1;
}

// ---------------- outputs ----------------
__global__ void xout_kernel(const float* __restrict__ x, float* __restrict__ ox) {
    __shared__ float tile[32][33];
    int t0 = blockIdx.x * 32, c0 = blockIdx.y * 32, b = blockIdx.z;
    int tx = threadIdx.x, ty = threadIdx.y;
    for (int i = ty; i < 32; i += 8)
        tile[i][tx] = x[((size_t)(b * TD + t0 + i) * CD) + c0 + tx];
    __syncthreads();
    for (int i = ty; i < 32; i += 8)
        ox[((size_t)(b * CD + c0 + i) * TD) + t0 + tx] = tile[tx][i];
}

__global__ void maskout_kernel(const int* __restrict__ lens, float* __restrict__ om) {
    int idx = blockIdx.x * 256 + threadIdx.x;
    int b = idx >> 10, t = idx & 1023;
    om[idx] = (t < lens[b]) ? 1.0f : 0.0f;
}

__global__ __launch_bounds__(384)
void stats_kernel(const float* __restrict__ x, const float* __restrict__ pw,
                  const float* __restrict__ pb, const int* __restrict__ lens,
                  float* __restrict__ om, float* __restrict__ ol) {
    int m0 = blockIdx.x * 8;
    __shared__ float sx[8][CD];
    int tid = threadIdx.x;
    for (int i = tid; i < 8 * CD / 4; i += 384)
        ((float4*)sx)[i] = ((const float4*)(x + (size_t)m0 * CD))[i];
    __syncthreads();

    float acc[8];
#pragma unroll
    for (int t = 0; t < 8; t++) acc[t] = 0.f;
    const float4* w4 = (const float4*)(pw + (size_t)tid * CD);
#pragma unroll 8
    for (int i = 0; i < CD / 4; i++) {
        float4 w = w4[i];
#pragma unroll
        for (int t = 0; t < 8; t++) {
            float4 xv = *(const float4*)&sx[t][i * 4];
            acc[t] += w.x * xv.x + w.y * xv.y + w.z * xv.z + w.w * xv.w;
        }
    }
    float bias = pb[tid];
#pragma unroll
    for (int t = 0; t < 8; t++) {
        int m = m0 + t;
        int b = m >> 10, tt = m & 1023;
        float msk = (tt < lens[b]) ? 1.0f : 0.0f;
        float val = (acc[t] + bias) * msk;
        if (tid < NOUT) om[((size_t)b * NOUT + tid) * TD + tt] = val;
        else            ol[((size_t)b * NOUT + (tid - NOUT)) * TD + tt] = val;
    }
}

// ---------------- launch ----------------
extern "C" void kernel_launch(void* const* d_in, const int* in_sizes, int n_in,
                              void* d_out, int out_size) {
    const float* emb  = (const float*)d_in[0];
    const float* Wq   = (const float*)d_in[1];
    const float* Wk   = (const float*)d_in[2];
    const float* Wv   = (const float*)d_in[3];
    const float* Wo   = (const float*)d_in[4];
    const float* bq   = (const float*)d_in[5];
    const float* bk   = (const float*)d_in[6];
    const float* bv   = (const float*)d_in[7];
    const float* bo   = (const float*)d_in[8];
    const float* relk = (const float*)d_in[9];
    const float* relv = (const float*)d_in[10];
    const float* ln1g = (const float*)d_in[11];
    const float* ln1b = (const float*)d_in[12];
    const float* ln2g = (const float*)d_in[13];
    const float* ln2b = (const float*)d_in[14];
    const float* fw1  = (const float*)d_in[15];
    const float* fb1  = (const float*)d_in[16];
    const float* fw2  = (const float*)d_in[17];
    const float* fb2  = (const float*)d_in[18];
    const float* pw   = (const float*)d_in[19];
    const float* pb   = (const float*)d_in[20];
    const int*   tok  = (const int*)d_in[21];
    const int*   lens = (const int*)d_in[22];

    float* out      = (float*)d_out;
    float* out_x    = out;
    float* out_m    = out_x + (size_t)BD * CD * TD;
    float* out_logs = out_m + (size_t)BD * NOUT * TD;
    float* out_mask = out_logs + (size_t)BD * NOUT * TD;

    float *px, *pq, *pk, *pv, *pt, *pf;
    u16 *pkhi, *pklo, *pvthi, *pvtlo;
    cudaGetSymbolAddress((void**)&px, g_x);
    cudaGetSymbolAddress((void**)&pq, g_q);
    cudaGetSymbolAddress((void**)&pk, g_k);
    cudaGetSymbolAddress((void**)&pv, g_v);
    cudaGetSymbolAddress((void**)&pt, g_t);
    cudaGetSymbolAddress((void**)&pf, g_f);
    cudaGetSymbolAddress((void**)&pkhi, g_khi);
    cudaGetSymbolAddress((void**)&pklo, g_klo);
    cudaGetSymbolAddress((void**)&pvthi, g_vthi);
    cudaGetSymbolAddress((void**)&pvtlo, g_vtlo);

    cudaFuncSetAttribute(attn_tc,
                         cudaFuncAttributeMaxDynamicSharedMemorySize, ATTN_SMEM);

    embed_kernel<<<MROWS * CD / 256, 256>>>(emb, tok);

    dim3 gQKV(CD / 128, MROWS / 128, 3);
    dim3 gC(CD / 128, MROWS / 128);
    dim3 gF(FCD / 128, MROWS / 128);
    dim3 gVT(TD / 32, CD / 32, BD);
    for (int i = 0; i < NL; i++) {
        const size_t wcc = (size_t)i * CD * CD;
        qkv_tc<<<gQKV, 256>>>(px, Wq + wcc, Wk + wcc, Wv + wcc,
                              bq + i * CD, bk + i * CD, bv + i * CD,
                              pq, pk, pv);
        kcvt_kernel<<<MROWS * CD / 512, 256>>>(pk);
        vtrans_kernel<<<gVT, dim3(32, 8)>>>(pv);
        attn_tc<<<dim3(TD / QB, NH, BD), 512, ATTN_SMEM>>>(
            pq, pkhi, pklo, pvthi, pvtlo,
            relk + (size_t)i * 9 * HD_, relv + (size_t)i * 9 * HD_, lens, pt);
        tgemm<<<gC, 256>>>(pt, Wo + wcc, bo + i * CD, pq, CD, CD, 0);
        add_ln_kernel<<<MROWS / 8, 256>>>(px, pq, ln1g + i * CD, ln1b + i * CD,
                                          px, lens, 0);
        tgemm<<<gF, 256>>>(px, fw1 + (size_t)i * CD * FCD, fb1 + i * FCD,
                           pf, FCD, CD, 1);
        tgemm<<<gC, 256>>>(pf, fw2 + (size_t)i * FCD * CD, fb2 + i * CD,
                           pt, CD, FCD, 0);
        add_ln_kernel<<<MROWS / 8, 256>>>(px, pt, ln2g + i * CD, ln2b + i * CD,
                                          px, lens, 1);
    }

    xout_kernel<<<gVT, dim3(32, 8)>>>(px, out_x);
    maskout_kernel<<<BD * TD / 256, 256>>>(lens, out_mask);
    stats_kernel<<<MROWS / 8, 384>>>(px, pw, pb, lens, out_m, out_logs);
}